// round 2
// baseline (speedup 1.0000x reference)
#include <cuda_runtime.h>

#define NND 100000
#define NE  1000000

// ---------------- device scratch (static, allocation-free) ----------------
__device__ float g_agg1[(size_t)NND * 64];   // layer-1 neighbor sum of x
__device__ float g_agg2[(size_t)NND * 64];   // layer-2 neighbor sum of p
__device__ float g_h   [(size_t)NND * 128];  // hidden activations
__device__ float g_p   [(size_t)NND * 64];   // h @ W2l (pre-aggregation)
__device__ float g_rinv[NND];                // 1 / max(cnt,1)
__device__ int   g_cnt [NND];
__device__ int   g_src [NE];
__device__ int   g_dst [NE];

// ---------------- init: zero accumulators, copy+clamp int32 edges ----------------
__global__ void k_init(const int* __restrict__ ei) {
    int i = blockIdx.x * 256 + threadIdx.x;          // exactly NND*64 = 6.4M threads
    g_agg1[i] = 0.f;
    g_agg2[i] = 0.f;
    if (i < NND) g_cnt[i] = 0;
    if (i < NE) {
        int s = ei[i];
        int d = ei[NE + i];
        g_src[i] = (s < 0) ? 0 : (s >= NND ? NND - 1 : s);   // defensive clamp
        g_dst[i] = (d < 0) ? 0 : (d >= NND ? NND - 1 : d);
    }
}

// ---------------- scatter: agg[dst] += feat[src] (64 floats/edge) ----------------
// 16 threads per edge, one red.global.add.v4.f32 each. LAYER==1 also counts degrees.
template <int LAYER>
__global__ void k_scatter(const float* __restrict__ xin) {
    int t = blockIdx.x * 256 + threadIdx.x;          // exactly NE*16 = 16M threads
    int e = t >> 4;
    int c = t & 15;
    int s = g_src[e];
    int d = g_dst[e];
    const float* feat = (LAYER == 1) ? xin : g_p;
    float*       agg  = (LAYER == 1) ? g_agg1 : g_agg2;
    float4 v = __ldg((const float4*)feat + (size_t)s * 16 + c);
    float* a = agg + (size_t)d * 64 + (c << 2);
    asm volatile("red.global.add.v4.f32 [%0], {%1,%2,%3,%4};"
                 :: "l"(a), "f"(v.x), "f"(v.y), "f"(v.z), "f"(v.w) : "memory");
    if (LAYER == 1 && c == 0) atomicAdd(&g_cnt[d], 1);
}

// ---------------- GEMM1: h = relu( (agg1*rinv) @ W1l + x @ W1r + b1 ) ----------------
// 64 nodes/block in 4 subtiles of 16; 256 thr = 16 nodes x 16 col-groups (8 cols each).
extern __shared__ float sm[];
__global__ __launch_bounds__(256, 2)
void k_gemm1(const float* __restrict__ x, const float* __restrict__ W1l,
             const float* __restrict__ W1r, const float* __restrict__ b1) {
    float* Wl = sm;                 // 64x128
    float* Wr = sm + 8192;          // 64x128
    float* xs = sm + 16384;         // 16 x 65 (padded)
    float* as = xs + 16 * 65;       // 16 x 65 (padded, pre-scaled by rinv)
    int tid = threadIdx.x;

    for (int i = tid; i < 2048; i += 256) {
        ((float4*)Wl)[i] = __ldg((const float4*)W1l + i);
        ((float4*)Wr)[i] = __ldg((const float4*)W1r + i);
    }

    int nl = tid >> 4;              // node-in-subtile 0..15
    int cg = tid & 15;              // col-group 0..15 -> cols cg*8..cg*8+7
    float bias[8];
    {
        float4 b0 = __ldg((const float4*)b1 + cg * 2);
        float4 b1v = __ldg((const float4*)b1 + cg * 2 + 1);
        bias[0]=b0.x; bias[1]=b0.y; bias[2]=b0.z; bias[3]=b0.w;
        bias[4]=b1v.x; bias[5]=b1v.y; bias[6]=b1v.z; bias[7]=b1v.w;
    }

    int nodeB = blockIdx.x * 64;
    for (int ii = 0; ii < 4; ii++) {
        int node0 = nodeB + ii * 16;
        __syncthreads();            // protect smem from previous subtile / weight load
        {
            int n = tid >> 4, f = tid & 15;          // 16 nodes x 16 float4
            int node = node0 + n;
            float4 vx = make_float4(0.f, 0.f, 0.f, 0.f);
            float4 va = vx;
            float  ri = 1.f;
            if (node < NND) {
                vx = __ldg((const float4*)x + (size_t)node * 16 + f);
                va = *((const float4*)g_agg1 + (size_t)node * 16 + f);
                int cn = g_cnt[node];
                ri = 1.f / (float)(cn < 1 ? 1 : cn);
                if (f == 0) g_rinv[node] = ri;
            }
            float* xr = xs + n * 65;
            xr[f*4+0]=vx.x; xr[f*4+1]=vx.y; xr[f*4+2]=vx.z; xr[f*4+3]=vx.w;
            float* ar = as + n * 65;
            ar[f*4+0]=va.x*ri; ar[f*4+1]=va.y*ri; ar[f*4+2]=va.z*ri; ar[f*4+3]=va.w*ri;
        }
        __syncthreads();

        float acc[8];
        #pragma unroll
        for (int j = 0; j < 8; j++) acc[j] = bias[j];

        const float* arow = as + nl * 65;
        const float* xrow = xs + nl * 65;
        #pragma unroll 16
        for (int k = 0; k < 64; k++) {
            float a1 = arow[k];
            float a2 = xrow[k];
            float4 bl0 = *(const float4*)(Wl + k * 128 + cg * 8);
            float4 bl1 = *(const float4*)(Wl + k * 128 + cg * 8 + 4);
            float4 br0 = *(const float4*)(Wr + k * 128 + cg * 8);
            float4 br1 = *(const float4*)(Wr + k * 128 + cg * 8 + 4);
            acc[0] = fmaf(a1, bl0.x, fmaf(a2, br0.x, acc[0]));
            acc[1] = fmaf(a1, bl0.y, fmaf(a2, br0.y, acc[1]));
            acc[2] = fmaf(a1, bl0.z, fmaf(a2, br0.z, acc[2]));
            acc[3] = fmaf(a1, bl0.w, fmaf(a2, br0.w, acc[3]));
            acc[4] = fmaf(a1, bl1.x, fmaf(a2, br1.x, acc[4]));
            acc[5] = fmaf(a1, bl1.y, fmaf(a2, br1.y, acc[5]));
            acc[6] = fmaf(a1, bl1.z, fmaf(a2, br1.z, acc[6]));
            acc[7] = fmaf(a1, bl1.w, fmaf(a2, br1.w, acc[7]));
        }
        int node = node0 + nl;
        if (node < NND) {
            float4 o0 = make_float4(fmaxf(acc[0],0.f), fmaxf(acc[1],0.f),
                                    fmaxf(acc[2],0.f), fmaxf(acc[3],0.f));
            float4 o1 = make_float4(fmaxf(acc[4],0.f), fmaxf(acc[5],0.f),
                                    fmaxf(acc[6],0.f), fmaxf(acc[7],0.f));
            ((float4*)g_h)[(size_t)node * 32 + cg * 2]     = o0;
            ((float4*)g_h)[(size_t)node * 32 + cg * 2 + 1] = o1;
        }
    }
}

// ---------------- GEMM2: p = h @ W2l ;  out = h @ W2r + b2 (partial) ----------------
// 64 nodes/block in 2 subtiles of 32; 256 thr = 32 nodes x 8 col-groups (8 cols each).
__global__ __launch_bounds__(256, 2)
void k_gemm2(const float* __restrict__ W2l, const float* __restrict__ W2r,
             const float* __restrict__ b2, float* __restrict__ out) {
    float* Wl = sm;                 // 128x64
    float* Wr = sm + 8192;          // 128x64
    float* hs = sm + 16384;         // 32 x 129 (padded)
    int tid = threadIdx.x;

    for (int i = tid; i < 2048; i += 256) {
        ((float4*)Wl)[i] = __ldg((const float4*)W2l + i);
        ((float4*)Wr)[i] = __ldg((const float4*)W2r + i);
    }

    int nl = tid >> 3;              // node-in-subtile 0..31
    int cg = tid & 7;               // col-group 0..7 -> cols cg*8..cg*8+7
    float bias[8];
    {
        float4 b0 = __ldg((const float4*)b2 + cg * 2);
        float4 b1v = __ldg((const float4*)b2 + cg * 2 + 1);
        bias[0]=b0.x; bias[1]=b0.y; bias[2]=b0.z; bias[3]=b0.w;
        bias[4]=b1v.x; bias[5]=b1v.y; bias[6]=b1v.z; bias[7]=b1v.w;
    }

    int nodeB = blockIdx.x * 64;
    for (int ii = 0; ii < 2; ii++) {
        int node0 = nodeB + ii * 32;
        __syncthreads();
        for (int i = tid; i < 1024; i += 256) {     // 32 nodes x 32 float4
            int n = i >> 5, f = i & 31;
            int node = node0 + n;
            float4 v = make_float4(0.f, 0.f, 0.f, 0.f);
            if (node < NND) v = __ldg((const float4*)g_h + (size_t)node * 32 + f);
            float* hr = hs + n * 129;
            hr[f*4+0]=v.x; hr[f*4+1]=v.y; hr[f*4+2]=v.z; hr[f*4+3]=v.w;
        }
        __syncthreads();

        float accl[8], accr[8];
        #pragma unroll
        for (int j = 0; j < 8; j++) { accl[j] = 0.f; accr[j] = bias[j]; }

        const float* hrow = hs + nl * 129;
        #pragma unroll 16
        for (int k = 0; k < 128; k++) {
            float a = hrow[k];
            float4 bl0 = *(const float4*)(Wl + k * 64 + cg * 8);
            float4 bl1 = *(const float4*)(Wl + k * 64 + cg * 8 + 4);
            float4 br0 = *(const float4*)(Wr + k * 64 + cg * 8);
            float4 br1 = *(const float4*)(Wr + k * 64 + cg * 8 + 4);
            accl[0] = fmaf(a, bl0.x, accl[0]);  accr[0] = fmaf(a, br0.x, accr[0]);
            accl[1] = fmaf(a, bl0.y, accl[1]);  accr[1] = fmaf(a, br0.y, accr[1]);
            accl[2] = fmaf(a, bl0.z, accl[2]);  accr[2] = fmaf(a, br0.z, accr[2]);
            accl[3] = fmaf(a, bl0.w, accl[3]);  accr[3] = fmaf(a, br0.w, accr[3]);
            accl[4] = fmaf(a, bl1.x, accl[4]);  accr[4] = fmaf(a, br1.x, accr[4]);
            accl[5] = fmaf(a, bl1.y, accl[5]);  accr[5] = fmaf(a, br1.y, accr[5]);
            accl[6] = fmaf(a, bl1.z, accl[6]);  accr[6] = fmaf(a, br1.z, accr[6]);
            accl[7] = fmaf(a, bl1.w, accl[7]);  accr[7] = fmaf(a, br1.w, accr[7]);
        }
        int node = node0 + nl;
        if (node < NND) {
            ((float4*)g_p)[(size_t)node * 16 + cg * 2] =
                make_float4(accl[0], accl[1], accl[2], accl[3]);
            ((float4*)g_p)[(size_t)node * 16 + cg * 2 + 1] =
                make_float4(accl[4], accl[5], accl[6], accl[7]);
            ((float4*)out)[(size_t)node * 16 + cg * 2] =
                make_float4(accr[0], accr[1], accr[2], accr[3]);
            ((float4*)out)[(size_t)node * 16 + cg * 2 + 1] =
                make_float4(accr[4], accr[5], accr[6], accr[7]);
        }
    }
}

// ---------------- finalize: out += agg2 * rinv ----------------
__global__ void k_final(float* __restrict__ out) {
    int t = blockIdx.x * 256 + threadIdx.x;     // exactly NND*16 = 1.6M threads
    int node = t >> 4;
    float ri = g_rinv[node];
    float4 a = ((const float4*)g_agg2)[t];
    float4 o = ((float4*)out)[t];
    o.x = fmaf(a.x, ri, o.x);
    o.y = fmaf(a.y, ri, o.y);
    o.z = fmaf(a.z, ri, o.z);
    o.w = fmaf(a.w, ri, o.w);
    ((float4*)out)[t] = o;
}

// ---------------- launch ----------------
extern "C" void kernel_launch(void* const* d_in, const int* in_sizes, int n_in,
                              void* d_out, int out_size) {
    // Identify inputs by element count (robust to metadata ordering):
    //   x: 6,400,000   edge_index: 2,000,000 (int32! JAX x64 disabled)
    //   b1: 128        b2: 64
    //   W1l, W1r, W2l, W2r: 8192 each, taken in relative order.
    const float* x   = nullptr;
    const float* b1  = nullptr;
    const float* b2  = nullptr;
    const int*   ei  = nullptr;
    const float* W[4] = {nullptr, nullptr, nullptr, nullptr};
    int wn = 0;
    for (int i = 0; i < n_in; i++) {
        int sz = in_sizes[i];
        if      (sz == NND * 64)  x  = (const float*)d_in[i];
        else if (sz == 2 * NE)    ei = (const int*)d_in[i];
        else if (sz == 128)       b1 = (const float*)d_in[i];
        else if (sz == 64)        b2 = (const float*)d_in[i];
        else if (sz == 8192 && wn < 4) W[wn++] = (const float*)d_in[i];
    }
    const float* W1l = W[0];
    const float* W1r = W[1];
    const float* W2l = W[2];
    const float* W2r = W[3];
    float* out = (float*)d_out;

    const int SM1 = (16384 + 2 * 16 * 65) * 4;   // 73856 B
    const int SM2 = (16384 + 32 * 129) * 4;      // 82048 B
    cudaFuncSetAttribute(k_gemm1, cudaFuncAttributeMaxDynamicSharedMemorySize, SM1);
    cudaFuncSetAttribute(k_gemm2, cudaFuncAttributeMaxDynamicSharedMemorySize, SM2);

    int gemm_blocks = (NND + 63) / 64;           // 1563

    k_init<<<25000, 256>>>(ei);                  // NND*64 threads
    k_scatter<1><<<62500, 256>>>(x);             // NE*16 threads, also counts degrees
    k_gemm1<<<gemm_blocks, 256, SM1>>>(x, W1l, W1r, b1);
    k_gemm2<<<gemm_blocks, 256, SM2>>>(W2l, W2r, b2, out);
    k_scatter<2><<<62500, 256>>>(nullptr);       // p -> agg2
    k_final<<<6250, 256>>>(out);                 // NND*16 threads
}

// round 3
// speedup vs baseline: 2.3727x; 2.3727x over previous
#include <cuda_runtime.h>

#define NND 100000
#define NE  1000000

// ---------------- device scratch (static, allocation-free) ----------------
__device__ float g_agg1[(size_t)NND * 64];   // layer-1 neighbor sum of x
__device__ float g_agg2[(size_t)NND * 64];   // layer-2 neighbor sum of p
__device__ float g_h   [(size_t)NND * 128];  // hidden activations
__device__ float g_p   [(size_t)NND * 64];   // h @ W2l (pre-aggregation)
__device__ float g_rinv[NND];                // 1 / max(cnt,1)
__device__ int   g_cnt [NND];
__device__ int   g_src [NE];
__device__ int   g_dst [NE];

// ---------------- init: zero accumulators, copy+clamp int32 edges ----------------
__global__ void k_init(const int* __restrict__ ei) {
    int i = blockIdx.x * 256 + threadIdx.x;          // exactly NND*64 = 6.4M threads
    g_agg1[i] = 0.f;
    g_agg2[i] = 0.f;
    if (i < NND) g_cnt[i] = 0;
    if (i < NE) {
        int s = ei[i];
        int d = ei[NE + i];
        g_src[i] = (s < 0) ? 0 : (s >= NND ? NND - 1 : s);
        g_dst[i] = (d < 0) ? 0 : (d >= NND ? NND - 1 : d);
    }
}

// ---------------- scatter: agg[dst] += feat[src] (64 floats/edge) ----------------
template <int LAYER>
__global__ void k_scatter(const float* __restrict__ xin) {
    int t = blockIdx.x * 256 + threadIdx.x;          // exactly NE*16 = 16M threads
    int e = t >> 4;
    int c = t & 15;
    int s = g_src[e];
    int d = g_dst[e];
    const float* feat = (LAYER == 1) ? xin : g_p;
    float*       agg  = (LAYER == 1) ? g_agg1 : g_agg2;
    float4 v = __ldg((const float4*)feat + (size_t)s * 16 + c);
    float* a = agg + (size_t)d * 64 + (c << 2);
    asm volatile("red.global.add.v4.f32 [%0], {%1,%2,%3,%4};"
                 :: "l"(a), "f"(v.x), "f"(v.y), "f"(v.z), "f"(v.w) : "memory");
    if (LAYER == 1 && c == 0) atomicAdd(&g_cnt[d], 1);
}

// ---------------- GEMM1: h = relu( (agg1*rinv) @ W1l + x @ W1r + b1 ) ----------------
// Block: 64 nodes x 128 cols. 256 thr: cg = tid&15 (8 cols), nq = tid>>4 (4 nodes).
// Each thread: 4 nodes x 8 cols = 32 accumulators x 2 input GEMMs fused.
extern __shared__ float sm[];
__global__ __launch_bounds__(256, 2)
void k_gemm1(const float* __restrict__ x, const float* __restrict__ W1l,
             const float* __restrict__ W1r, const float* __restrict__ b1) {
    float* Wl = sm;                        // 64 x 128
    float* Wr = sm + 8192;                 // 64 x 128
    float* as = sm + 16384;                // 64 x 65  (agg1 * rinv)
    float* xs = as + 64 * 65;              // 64 x 65
    int tid = threadIdx.x;
    int nodeB = blockIdx.x * 64;

    for (int i = tid; i < 2048; i += 256) {
        ((float4*)Wl)[i] = __ldg((const float4*)W1l + i);
        ((float4*)Wr)[i] = __ldg((const float4*)W1r + i);
    }
    // Stage A tiles: 64 nodes x 16 float4, scaled by rinv.
    for (int i = tid; i < 1024; i += 256) {
        int n = i >> 4, f = i & 15;
        int node = nodeB + n;
        float4 vx = make_float4(0.f, 0.f, 0.f, 0.f);
        float4 va = vx;
        float  ri = 1.f;
        if (node < NND) {
            vx = __ldg((const float4*)x + (size_t)node * 16 + f);
            va = *((const float4*)g_agg1 + (size_t)node * 16 + f);
            int cn = g_cnt[node];
            ri = 1.f / (float)(cn < 1 ? 1 : cn);
            if (f == 0) g_rinv[node] = ri;
        }
        float* xr = xs + n * 65;
        xr[f*4+0]=vx.x; xr[f*4+1]=vx.y; xr[f*4+2]=vx.z; xr[f*4+3]=vx.w;
        float* ar = as + n * 65;
        ar[f*4+0]=va.x*ri; ar[f*4+1]=va.y*ri; ar[f*4+2]=va.z*ri; ar[f*4+3]=va.w*ri;
    }
    __syncthreads();

    int cg = tid & 15;               // col group -> cols cg*8..+7
    int nq = tid >> 4;               // node quad -> nodes nq*4..+3
    int c0 = cg * 8;
    int n0 = nq * 4;

    float bias[8];
    {
        float4 b0 = __ldg((const float4*)b1 + cg * 2);
        float4 b1v = __ldg((const float4*)b1 + cg * 2 + 1);
        bias[0]=b0.x; bias[1]=b0.y; bias[2]=b0.z; bias[3]=b0.w;
        bias[4]=b1v.x; bias[5]=b1v.y; bias[6]=b1v.z; bias[7]=b1v.w;
    }
    float acc[4][8];
    #pragma unroll
    for (int j = 0; j < 4; j++)
        #pragma unroll
        for (int q = 0; q < 8; q++) acc[j][q] = bias[q];

    #pragma unroll 8
    for (int k = 0; k < 64; k++) {
        float a1v[4], a2v[4];
        #pragma unroll
        for (int j = 0; j < 4; j++) {
            a1v[j] = as[(n0 + j) * 65 + k];
            a2v[j] = xs[(n0 + j) * 65 + k];
        }
        float4 l0 = *(const float4*)(Wl + k * 128 + c0);
        float4 l1 = *(const float4*)(Wl + k * 128 + c0 + 4);
        float4 r0 = *(const float4*)(Wr + k * 128 + c0);
        float4 r1 = *(const float4*)(Wr + k * 128 + c0 + 4);
        #pragma unroll
        for (int j = 0; j < 4; j++) {
            float a1 = a1v[j], a2 = a2v[j];
            acc[j][0] = fmaf(a1, l0.x, fmaf(a2, r0.x, acc[j][0]));
            acc[j][1] = fmaf(a1, l0.y, fmaf(a2, r0.y, acc[j][1]));
            acc[j][2] = fmaf(a1, l0.z, fmaf(a2, r0.z, acc[j][2]));
            acc[j][3] = fmaf(a1, l0.w, fmaf(a2, r0.w, acc[j][3]));
            acc[j][4] = fmaf(a1, l1.x, fmaf(a2, r1.x, acc[j][4]));
            acc[j][5] = fmaf(a1, l1.y, fmaf(a2, r1.y, acc[j][5]));
            acc[j][6] = fmaf(a1, l1.z, fmaf(a2, r1.z, acc[j][6]));
            acc[j][7] = fmaf(a1, l1.w, fmaf(a2, r1.w, acc[j][7]));
        }
    }
    #pragma unroll
    for (int j = 0; j < 4; j++) {
        int node = nodeB + n0 + j;
        if (node < NND) {
            float4 o0 = make_float4(fmaxf(acc[j][0],0.f), fmaxf(acc[j][1],0.f),
                                    fmaxf(acc[j][2],0.f), fmaxf(acc[j][3],0.f));
            float4 o1 = make_float4(fmaxf(acc[j][4],0.f), fmaxf(acc[j][5],0.f),
                                    fmaxf(acc[j][6],0.f), fmaxf(acc[j][7],0.f));
            ((float4*)g_h)[(size_t)node * 32 + cg * 2]     = o0;
            ((float4*)g_h)[(size_t)node * 32 + cg * 2 + 1] = o1;
        }
    }
}

// ---------------- GEMM2: p = h @ W2l ;  out = h @ W2r + b2 (partial) ----------------
// Block: 64 nodes x 128 "virtual" cols (cols 0-63 -> W2l/p, 64-127 -> W2r/out).
// 256 thr: cg = tid&15, nq = tid>>4. Each thread: 4 nodes x 8 cols of ONE matrix.
__global__ __launch_bounds__(256, 2)
void k_gemm2(const float* __restrict__ W2l, const float* __restrict__ W2r,
             const float* __restrict__ b2, float* __restrict__ out) {
    float* Wl = sm;                        // 128 x 64
    float* Wr = sm + 8192;                 // 128 x 64
    float* hs = sm + 16384;                // 64 x 129
    int tid = threadIdx.x;
    int nodeB = blockIdx.x * 64;

    for (int i = tid; i < 2048; i += 256) {
        ((float4*)Wl)[i] = __ldg((const float4*)W2l + i);
        ((float4*)Wr)[i] = __ldg((const float4*)W2r + i);
    }
    for (int i = tid; i < 2048; i += 256) {      // 64 nodes x 32 float4
        int n = i >> 5, f = i & 31;
        int node = nodeB + n;
        float4 v = make_float4(0.f, 0.f, 0.f, 0.f);
        if (node < NND) v = __ldg((const float4*)g_h + (size_t)node * 32 + f);
        float* hr = hs + n * 129;
        hr[f*4+0]=v.x; hr[f*4+1]=v.y; hr[f*4+2]=v.z; hr[f*4+3]=v.w;
    }
    __syncthreads();

    int cg = tid & 15;
    int nq = tid >> 4;
    int n0 = nq * 4;
    bool isR = (cg >= 8);                  // right matrix -> out, with bias
    int c0 = (cg & 7) * 8;
    const float* W = isR ? Wr : Wl;

    float acc[4][8];
    if (isR) {
        float4 b0 = __ldg((const float4*)b2 + (cg & 7) * 2);
        float4 b1v = __ldg((const float4*)b2 + (cg & 7) * 2 + 1);
        #pragma unroll
        for (int j = 0; j < 4; j++) {
            acc[j][0]=b0.x; acc[j][1]=b0.y; acc[j][2]=b0.z; acc[j][3]=b0.w;
            acc[j][4]=b1v.x; acc[j][5]=b1v.y; acc[j][6]=b1v.z; acc[j][7]=b1v.w;
        }
    } else {
        #pragma unroll
        for (int j = 0; j < 4; j++)
            #pragma unroll
            for (int q = 0; q < 8; q++) acc[j][q] = 0.f;
    }

    #pragma unroll 8
    for (int k = 0; k < 128; k++) {
        float av[4];
        #pragma unroll
        for (int j = 0; j < 4; j++) av[j] = hs[(n0 + j) * 129 + k];
        float4 w0 = *(const float4*)(W + k * 64 + c0);
        float4 w1 = *(const float4*)(W + k * 64 + c0 + 4);
        #pragma unroll
        for (int j = 0; j < 4; j++) {
            float a = av[j];
            acc[j][0] = fmaf(a, w0.x, acc[j][0]);
            acc[j][1] = fmaf(a, w0.y, acc[j][1]);
            acc[j][2] = fmaf(a, w0.z, acc[j][2]);
            acc[j][3] = fmaf(a, w0.w, acc[j][3]);
            acc[j][4] = fmaf(a, w1.x, acc[j][4]);
            acc[j][5] = fmaf(a, w1.y, acc[j][5]);
            acc[j][6] = fmaf(a, w1.z, acc[j][6]);
            acc[j][7] = fmaf(a, w1.w, acc[j][7]);
        }
    }
    float* dst = isR ? out : g_p;
    #pragma unroll
    for (int j = 0; j < 4; j++) {
        int node = nodeB + n0 + j;
        if (node < NND) {
            ((float4*)dst)[(size_t)node * 16 + (cg & 7) * 2] =
                make_float4(acc[j][0], acc[j][1], acc[j][2], acc[j][3]);
            ((float4*)dst)[(size_t)node * 16 + (cg & 7) * 2 + 1] =
                make_float4(acc[j][4], acc[j][5], acc[j][6], acc[j][7]);
        }
    }
}

// ---------------- finalize: out += agg2 * rinv ----------------
__global__ void k_final(float* __restrict__ out) {
    int t = blockIdx.x * 256 + threadIdx.x;     // exactly NND*16 = 1.6M threads
    int node = t >> 4;
    float ri = g_rinv[node];
    float4 a = ((const float4*)g_agg2)[t];
    float4 o = ((float4*)out)[t];
    o.x = fmaf(a.x, ri, o.x);
    o.y = fmaf(a.y, ri, o.y);
    o.z = fmaf(a.z, ri, o.z);
    o.w = fmaf(a.w, ri, o.w);
    ((float4*)out)[t] = o;
}

// ---------------- launch ----------------
extern "C" void kernel_launch(void* const* d_in, const int* in_sizes, int n_in,
                              void* d_out, int out_size) {
    const float* x   = nullptr;
    const float* b1  = nullptr;
    const float* b2  = nullptr;
    const int*   ei  = nullptr;
    const float* W[4] = {nullptr, nullptr, nullptr, nullptr};
    int wn = 0;
    for (int i = 0; i < n_in; i++) {
        int sz = in_sizes[i];
        if      (sz == NND * 64)  x  = (const float*)d_in[i];
        else if (sz == 2 * NE)    ei = (const int*)d_in[i];
        else if (sz == 128)       b1 = (const float*)d_in[i];
        else if (sz == 64)        b2 = (const float*)d_in[i];
        else if (sz == 8192 && wn < 4) W[wn++] = (const float*)d_in[i];
    }
    const float* W1l = W[0];
    const float* W1r = W[1];
    const float* W2l = W[2];
    const float* W2r = W[3];
    float* out = (float*)d_out;

    const int SM1 = (16384 + 2 * 64 * 65) * 4;   // 98816 B
    const int SM2 = (16384 + 64 * 129) * 4;      // 98560 B
    cudaFuncSetAttribute(k_gemm1, cudaFuncAttributeMaxDynamicSharedMemorySize, SM1);
    cudaFuncSetAttribute(k_gemm2, cudaFuncAttributeMaxDynamicSharedMemorySize, SM2);

    int gemm_blocks = (NND + 63) / 64;           // 1563

    k_init<<<25000, 256>>>(ei);                  // NND*64 threads
    k_scatter<1><<<62500, 256>>>(x);             // NE*16 threads, also counts degrees
    k_gemm1<<<gemm_blocks, 256, SM1>>>(x, W1l, W1r, b1);
    k_gemm2<<<gemm_blocks, 256, SM2>>>(W2l, W2r, b2, out);
    k_scatter<2><<<62500, 256>>>(nullptr);       // p -> agg2
    k_final<<<6250, 256>>>(out);                 // NND*16 threads
}